// round 1
// baseline (speedup 1.0000x reference)
#include <cuda_runtime.h>

#define Nn   100000
#define Ee   3200000
#define HID  64
#define INF  500
#define CLS  40
#define KK   10

// ---------------- device scratch (static; never allocated at runtime) ----------------
__device__ float g_buf0[Nn*HID];
__device__ float g_buf1[Nn*HID];
__device__ float g_buf2[Nn*HID];
__device__ float g_zbuf[Nn*HID];            // never written -> stays zero
__device__ float g_rst [Nn*HID];
__device__ unsigned long long g_edge[Ee];   // packed {src, w}
__device__ int   g_rowptr[Nn+1];
__device__ int   g_cnt[Nn];
__device__ int   g_cur[Nn];
__device__ int   g_bsum[128];
__device__ float g_acc[256];                // d1[64] | d2[64] | d12[64] | ss[64]
__device__ float g_coef[192];               // c1'[64] | c2'[64] | ra[64]
__device__ float g_inv[(KK+2)*HID];         // slot(i) at (i+1)*64 ; slot(-1) stays zero

__device__ __forceinline__ float* bufptr(int i){
    return (i==0)? g_buf0 : (i==1)? g_buf1 : (i==2)? g_buf2 : g_zbuf;
}

// ---------------- init ----------------
__global__ void k_zero(){
    int i = blockIdx.x*blockDim.x + threadIdx.x;
    if (i < Nn){ g_cnt[i] = 0; g_cur[i] = 0; }
    if (i < 256) g_acc[i] = 0.f;
}

// ---------------- CSR build ----------------
__global__ void k_count(const int* __restrict__ dst){
    int e = blockIdx.x*blockDim.x + threadIdx.x;
    if (e < Ee) atomicAdd(&g_cnt[dst[e]], 1);
}

__global__ void k_scan1(){          // per-block inclusive scan of g_cnt chunks of 1024
    __shared__ int s[1024];
    int t = threadIdx.x;
    int base = blockIdx.x*1024;
    int v = (base + t < Nn) ? g_cnt[base + t] : 0;
    s[t] = v; __syncthreads();
    for (int d = 1; d < 1024; d <<= 1){
        int add = (t >= d) ? s[t-d] : 0;
        __syncthreads();
        s[t] += add;
        __syncthreads();
    }
    if (base + t < Nn) g_rowptr[base + t + 1] = s[t];
    if (t == 1023) g_bsum[blockIdx.x] = s[1023];
}

__global__ void k_scan2(int nb){    // exclusive scan of block sums (small)
    __shared__ int s[128];
    int t = threadIdx.x;
    if (t < nb) s[t] = g_bsum[t];
    __syncthreads();
    if (t == 0){
        int acc = 0;
        for (int b = 0; b < nb; b++){ int v = s[b]; s[b] = acc; acc += v; }
    }
    __syncthreads();
    if (t < nb) g_bsum[t] = s[t];
}

__global__ void k_scan3(){
    int i = blockIdx.x*blockDim.x + threadIdx.x;
    if (i == 0) g_rowptr[0] = 0;
    if (i < Nn) g_rowptr[i+1] += g_bsum[i >> 10];
}

__global__ void k_scatter(const int* __restrict__ src, const int* __restrict__ dst,
                          const float* __restrict__ w){
    int e = blockIdx.x*blockDim.x + threadIdx.x;
    if (e >= Ee) return;
    int d   = dst[e];
    int pos = g_rowptr[d] + atomicAdd(&g_cur[d], 1);
    unsigned long long pk = (unsigned int)src[e]
                          | ((unsigned long long)__float_as_uint(w[e]) << 32);
    g_edge[pos] = pk;
}

// ---------------- fc1: U0 = relu(feat@W1 + b1) + 1e-5*noise ; accumulate col sumsq ----------------
#define BM 128
#define BK 20
__global__ void k_fc1(const float* __restrict__ A, const float* __restrict__ W,
                      const float* __restrict__ b1, const float* __restrict__ noise){
    __shared__ float As[BK][132];
    __shared__ float Bs[BK][HID];
    __shared__ float scol[HID];
    int tid = threadIdx.x;
    int rowbase = blockIdx.x * BM;
    int tx = tid & 15;   // col group: cols tx*4..tx*4+3
    int ty = tid >> 4;   // row group: rows ty*8..ty*8+7
    float acc[8][4];
    #pragma unroll
    for (int i = 0; i < 8; i++)
        #pragma unroll
        for (int j = 0; j < 4; j++) acc[i][j] = 0.f;
    if (tid < HID) scol[tid] = 0.f;

    for (int k0 = 0; k0 < INF; k0 += BK){
        for (int f = tid; f < BM*BK; f += 256){
            int r = f / BK, k = f - r*BK;
            int grow = rowbase + r;
            As[k][r] = (grow < Nn) ? A[grow*INF + k0 + k] : 0.f;
        }
        for (int f = tid; f < BK*HID; f += 256){
            int k = f >> 6, c = f & 63;
            Bs[k][c] = W[(k0 + k)*HID + c];
        }
        __syncthreads();
        #pragma unroll
        for (int k = 0; k < BK; k++){
            float4 a0 = *(const float4*)&As[k][ty*8];
            float4 a1 = *(const float4*)&As[k][ty*8 + 4];
            float4 bq = *(const float4*)&Bs[k][tx*4];
            float av[8] = {a0.x,a0.y,a0.z,a0.w,a1.x,a1.y,a1.z,a1.w};
            float bv[4] = {bq.x,bq.y,bq.z,bq.w};
            #pragma unroll
            for (int i = 0; i < 8; i++)
                #pragma unroll
                for (int j = 0; j < 4; j++)
                    acc[i][j] = fmaf(av[i], bv[j], acc[i][j]);
        }
        __syncthreads();
    }

    float css[4] = {0.f,0.f,0.f,0.f};
    #pragma unroll
    for (int j = 0; j < 4; j++){
        int col = tx*4 + j;
        float bj = b1[col];
        #pragma unroll
        for (int i = 0; i < 8; i++){
            int grow = rowbase + ty*8 + i;
            if (grow < Nn){
                float v = fmaxf(acc[i][j] + bj, 0.f);
                v = fmaf(1e-5f, noise[grow*HID + col], v);
                g_buf0[grow*HID + col] = v;
                css[j] = fmaf(v, v, css[j]);
            }
        }
    }
    #pragma unroll
    for (int j = 0; j < 4; j++) atomicAdd(&scol[tx*4 + j], css[j]);
    __syncthreads();
    if (tid < HID) atomicAdd(&g_acc[192 + tid], scol[tid]);
}

// ---------------- SpMM: R = inv(prev) .* (A @ Uprev), one warp per dst row ----------------
__global__ void k_spmm(int uIdx, int rIdx, int invOff){
    const float* __restrict__ U = bufptr(uIdx);
    float* __restrict__ R = bufptr(rIdx);
    const float* __restrict__ inv = g_inv + invOff;
    int w    = (blockIdx.x*blockDim.x + threadIdx.x) >> 5;
    int lane = threadIdx.x & 31;
    if (w >= Nn) return;
    int e   = g_rowptr[w];
    int end = g_rowptr[w+1];
    float a0 = 0.f, a1 = 0.f;
    for (; e + 1 < end; e += 2){
        unsigned long long p0 = g_edge[e];
        unsigned long long p1 = g_edge[e+1];
        int   s0 = (int)(p0 & 0xffffffffu);
        float w0 = __uint_as_float((unsigned int)(p0 >> 32));
        int   s1 = (int)(p1 & 0xffffffffu);
        float w1 = __uint_as_float((unsigned int)(p1 >> 32));
        float2 v0 = *(const float2*)(U + (s0 << 6) + (lane << 1));
        float2 v1 = *(const float2*)(U + (s1 << 6) + (lane << 1));
        a0 = fmaf(w0, v0.x, a0); a1 = fmaf(w0, v0.y, a1);
        a0 = fmaf(w1, v1.x, a0); a1 = fmaf(w1, v1.y, a1);
    }
    if (e < end){
        unsigned long long p0 = g_edge[e];
        int   s0 = (int)(p0 & 0xffffffffu);
        float w0 = __uint_as_float((unsigned int)(p0 >> 32));
        float2 v0 = *(const float2*)(U + (s0 << 6) + (lane << 1));
        a0 = fmaf(w0, v0.x, a0); a1 = fmaf(w0, v0.y, a1);
    }
    float2 o;
    o.x = a0 * inv[lane*2];
    o.y = a1 * inv[lane*2 + 1];
    *(float2*)(R + (w << 6) + (lane << 1)) = o;
}

// ---------------- dots: d1 = <R,U1>, d2 = <R,U2>, d12 = <U1,U2> per column ----------------
__global__ void k_dots(int rIdx, int u1Idx, int u2Idx){
    const float2* __restrict__ R  = (const float2*)bufptr(rIdx);
    const float2* __restrict__ U1 = (const float2*)bufptr(u1Idx);
    const float2* __restrict__ U2 = (const float2*)bufptr(u2Idx);
    int tid = blockIdx.x*blockDim.x + threadIdx.x;
    int stride = gridDim.x*blockDim.x;
    int c = threadIdx.x & 31;
    float d1x=0.f,d1y=0.f,d2x=0.f,d2y=0.f,d3x=0.f,d3y=0.f;
    for (int i = tid; i < Nn*32; i += stride){
        float2 r = R[i], u1 = U1[i], u2 = U2[i];
        d1x = fmaf(r.x,  u1.x, d1x); d1y = fmaf(r.y,  u1.y, d1y);
        d2x = fmaf(r.x,  u2.x, d2x); d2y = fmaf(r.y,  u2.y, d2y);
        d3x = fmaf(u1.x, u2.x, d3x); d3y = fmaf(u1.y, u2.y, d3y);
    }
    __shared__ float s[192];
    if (threadIdx.x < 192) s[threadIdx.x] = 0.f;
    __syncthreads();
    atomicAdd(&s[      c*2], d1x); atomicAdd(&s[      c*2+1], d1y);
    atomicAdd(&s[ 64 + c*2], d2x); atomicAdd(&s[ 64 + c*2+1], d2y);
    atomicAdd(&s[128 + c*2], d3x); atomicAdd(&s[128 + c*2+1], d3y);
    __syncthreads();
    if (threadIdx.x < 192) atomicAdd(&g_acc[threadIdx.x], s[threadIdx.x]);
}

// ---------------- scalars A: Gram-Schmidt coefficients (MGS-exact via d12) ----------------
__global__ void k_scalA(const float* __restrict__ alpha, int i){
    int j = threadIdx.x;
    if (j >= 64) return;
    double inv1 = (double)g_inv[i*64 + j];       // inv_{i-1}
    double inv2 = (double)g_inv[(i-1)*64 + j];   // inv_{i-2}  (zeros for i==1)
    double d1  = (double)g_acc[j];
    double d2  = (double)g_acc[64 + j];
    double d12 = (double)g_acc[128 + j];
    g_coef[j]       = (float)(d1*inv1*inv1);                          // coeff on U1
    g_coef[64 + j]  = (float)(inv2*inv2*(d2 - inv1*inv1*d1*d12));     // coeff on U2 (MGS)
    g_coef[128 + j] = alpha[j*(KK+1) + (i-1)] * (float)inv1;          // rst coeff for h_{i-1}
    g_acc[j] = 0.f; g_acc[64 + j] = 0.f; g_acc[128 + j] = 0.f;
}

// ---------------- pass2: subtract projections in place, sumsq, deferred rst accumulation ----------------
__global__ void k_pass2(int rIdx, int u1Idx, int u2Idx, int first){
    float2* __restrict__ R  = (float2*)bufptr(rIdx);
    const float2* __restrict__ U1 = (const float2*)bufptr(u1Idx);
    const float2* __restrict__ U2 = (const float2*)bufptr(u2Idx);
    float2* __restrict__ RS = (float2*)g_rst;
    __shared__ float c1s[64], c2s[64], ras[64], sss[64];
    int t = threadIdx.x;
    if (t < 64){ c1s[t]=g_coef[t]; c2s[t]=g_coef[64+t]; ras[t]=g_coef[128+t]; sss[t]=0.f; }
    __syncthreads();
    int c = t & 31;
    float c1x=c1s[2*c], c1y=c1s[2*c+1];
    float c2x=c2s[2*c], c2y=c2s[2*c+1];
    float rax=ras[2*c], ray=ras[2*c+1];
    float ssx=0.f, ssy=0.f;
    int tid = blockIdx.x*blockDim.x + t;
    int stride = gridDim.x*blockDim.x;
    for (int i = tid; i < Nn*32; i += stride){
        float2 r = R[i], u1 = U1[i], u2 = U2[i];
        float wx = r.x - c1x*u1.x - c2x*u2.x;
        float wy = r.y - c1y*u1.y - c2y*u2.y;
        ssx = fmaf(wx, wx, ssx); ssy = fmaf(wy, wy, ssy);
        float2 o; o.x = wx; o.y = wy;
        R[i] = o;
        float2 rv;
        if (first){ rv.x = rax*u1.x;            rv.y = ray*u1.y; }
        else      { rv = RS[i]; rv.x = fmaf(rax, u1.x, rv.x); rv.y = fmaf(ray, u1.y, rv.y); }
        RS[i] = rv;
    }
    atomicAdd(&sss[2*c], ssx); atomicAdd(&sss[2*c+1], ssy);
    __syncthreads();
    if (t < 64) atomicAdd(&g_acc[192 + t], sss[t]);
}

// ---------------- scalars B: inv_i = 1/max(||h'||, 1e-8) ----------------
__global__ void k_scalB(int i){
    int j = threadIdx.x;
    if (j < 64){
        float ss  = g_acc[192 + j];
        float inv = 1.f / fmaxf(sqrtf(ss), 1e-8f);
        g_inv[(i+1)*64 + j] = inv;
        g_acc[192 + j] = 0.f;
    }
}

// ---------------- final: out = (rst + a_K*inv_K .* U_K) @ W2 + b2 ----------------
__global__ void k_out(const float* __restrict__ W2, const float* __restrict__ b2,
                      const float* __restrict__ alpha, float* __restrict__ out, int ukIdx){
    const float* __restrict__ UK = bufptr(ukIdx);
    __shared__ float Ts[128][65];
    __shared__ float Bs[HID][CLS + 1];
    __shared__ float ck[64];
    int tid = threadIdx.x;
    int rowbase = blockIdx.x * 128;
    if (tid < 64) ck[tid] = alpha[tid*(KK+1) + KK] * g_inv[(KK+1)*64 + tid];
    for (int f = tid; f < HID*CLS; f += 256) Bs[f / CLS][f % CLS] = W2[f];
    __syncthreads();
    for (int f = tid; f < 128*64; f += 256){
        int r = f >> 6, col = f & 63;
        int grow = rowbase + r;
        float v = 0.f;
        if (grow < Nn){
            int idx = grow*64 + col;
            v = g_rst[idx] + ck[col]*UK[idx];
        }
        Ts[r][col] = v;
    }
    __syncthreads();
    int tr = tid & 31;   // rows tr*4..tr*4+3
    int tc = tid >> 5;   // cols tc*5..tc*5+4
    float acc[4][5];
    #pragma unroll
    for (int i = 0; i < 4; i++)
        #pragma unroll
        for (int j = 0; j < 5; j++) acc[i][j] = 0.f;
    for (int k = 0; k < 64; k++){
        float a[4], bb[5];
        #pragma unroll
        for (int i = 0; i < 4; i++) a[i] = Ts[tr*4 + i][k];
        #pragma unroll
        for (int j = 0; j < 5; j++) bb[j] = Bs[k][tc*5 + j];
        #pragma unroll
        for (int i = 0; i < 4; i++)
            #pragma unroll
            for (int j = 0; j < 5; j++)
                acc[i][j] = fmaf(a[i], bb[j], acc[i][j]);
    }
    #pragma unroll
    for (int i = 0; i < 4; i++){
        int row = rowbase + tr*4 + i;
        if (row < Nn){
            #pragma unroll
            for (int j = 0; j < 5; j++){
                int col = tc*5 + j;
                out[row*CLS + col] = acc[i][j] + b2[col];
            }
        }
    }
}

// ---------------- launch ----------------
extern "C" void kernel_launch(void* const* d_in, const int* in_sizes, int n_in,
                              void* d_out, int out_size){
    (void)in_sizes; (void)n_in; (void)out_size;
    const float* feat  = (const float*)d_in[0];
    const float* noise = (const float*)d_in[1];
    const float* normA = (const float*)d_in[2];
    const float* W1    = (const float*)d_in[3];
    const float* b1    = (const float*)d_in[4];
    const float* W2    = (const float*)d_in[5];
    const float* b2    = (const float*)d_in[6];
    const float* alpha = (const float*)d_in[7];
    const int*   ei    = (const int*)  d_in[8];
    const int* src = ei;
    const int* dst = ei + Ee;
    float* out = (float*)d_out;

    const int TB = 256;
    // CSR build (per call; deterministic work)
    k_zero   <<<(Nn + TB - 1)/TB, TB>>>();
    k_count  <<<(Ee + TB - 1)/TB, TB>>>(dst);
    k_scan1  <<<(Nn + 1023)/1024, 1024>>>();
    k_scan2  <<<1, 128>>>((Nn + 1023)/1024);
    k_scan3  <<<(Nn + TB - 1)/TB, TB>>>();
    k_scatter<<<(Ee + TB - 1)/TB, TB>>>(src, dst, normA);

    // fc1 -> U0 (unnormalized) + column sumsq -> inv_0
    k_fc1  <<<(Nn + 127)/128, 256>>>(feat, W1, b1, noise);
    k_scalB<<<1, 64>>>(0);

    for (int i = 1; i <= KK; i++){
        int rIdx = i % 3;
        int u1   = (i + 2) % 3;              // U_{i-1}
        int u2   = (i == 1) ? 3 : (i + 1) % 3;  // U_{i-2} (zero buffer for i==1)
        k_spmm <<<(Nn*32 + TB - 1)/TB, TB>>>(u1, rIdx, i*64);
        k_dots <<<1520, TB>>>(rIdx, u1, u2);
        k_scalA<<<1, 64>>>(alpha, i);
        k_pass2<<<1520, TB>>>(rIdx, u1, u2, (i == 1) ? 1 : 0);
        k_scalB<<<1, 64>>>(i);
    }

    k_out<<<(Nn + 127)/128, 256>>>(W2, b2, alpha, out, KK % 3);
}